// round 12
// baseline (speedup 1.0000x reference)
#include <cuda_runtime.h>
#include <cuda_fp16.h>
#include <cstdint>

#define B_TOT   32768
#define T_LEN   40
#define F_DIM   92
#define H_DIM   64
#define G_DIM   256
#define ROWS    128
#define THREADS 512
#define KP      160      // k: 0..91 x, 92..95 pad, 96..159 h
#define NKC     10

// ---------------- SMEM byte offsets ----------------
#define W_OFF    0                 // fp16 W: [kc][blk=wc*4+gate][lane]{16B} : 10*16*512 = 81920
#define A_OFF    81920             // fp16 A frags x2 buffers: 2*40960
#define A_BUFSZ  40960
#define SB_OFF   163840            // bias fp32 [256] = 1024
#define SWD_OFF  164864            // Wd fp32 [64][2] = 512
#define SMEM_BYTES 165376

typedef unsigned int uint;

__device__ __forceinline__ void mma16816(float* d, const uint4& a, uint b0, uint b1) {
    asm volatile(
        "mma.sync.aligned.m16n8k16.row.col.f32.f16.f16.f32 "
        "{%0,%1,%2,%3}, {%4,%5,%6,%7}, {%8,%9}, {%0,%1,%2,%3};"
        : "+f"(d[0]), "+f"(d[1]), "+f"(d[2]), "+f"(d[3])
        : "r"(a.x), "r"(a.y), "r"(a.z), "r"(a.w), "r"(b0), "r"(b1));
}

// ---- f16x2 activation helpers ----
__device__ __forceinline__ uint htanh2u(uint x) {
    uint r; asm("tanh.approx.f16x2 %0, %1;" : "=r"(r) : "r"(x)); return r;
}
__device__ __forceinline__ uint pack_h2(float a, float b) {
    __half2 t = __floats2half2_rn(a, b);
    return *(uint*)&t;
}
// sigmoid(z0),sigmoid(z1) as half2: 0.5*tanh(0.5 z)+0.5
__device__ __forceinline__ uint sig2u(float z0, float z1) {
    uint th = htanh2u(pack_h2(0.5f * z0, 0.5f * z1));
    __half2 t = *(__half2*)&th;
    const __half2 h05 = __floats2half2_rn(0.5f, 0.5f);
    __half2 r = __hfma2(t, h05, h05);
    return *(uint*)&r;
}
__device__ __forceinline__ float2 h2f2(uint h) { return __half22float2(*(__half2*)&h); }

__device__ __forceinline__ float sig_acc(float x) { return 1.0f / (1.0f + __expf(-x)); }

// A-plane byte offset for element (row, k) within one buffer; k even pairs contiguous 4B
__device__ __forceinline__ int a_addr(int row, int k) {
    int mtg = row >> 4, r16 = row & 15, g = r16 & 7;
    int kc = k >> 4, kr = k & 15, tK = (kr >> 1) & 3;
    return (((mtg * NKC + kc) * 32 + g * 4 + tK) << 4) + ((kr >> 3) << 3) + ((r16 >> 3) << 2);
}

__global__ void __launch_bounds__(THREADS, 1)
lstm_hmma_kernel(const float* __restrict__ x,
                 const float* __restrict__ Wk,
                 const float* __restrict__ Wr,
                 const float* __restrict__ b,
                 const float* __restrict__ Wd,
                 const float* __restrict__ bd,
                 float* __restrict__ out)
{
    extern __shared__ char smem_c[];
    float* sb  = (float*)(smem_c + SB_OFF);
    float* sWd = (float*)(smem_c + SWD_OFF);

    const int tid  = threadIdx.x;
    const int w    = tid >> 5;
    const int lane = tid & 31;
    const int g    = lane >> 2;      // mma group id
    const int tt   = lane & 3;       // thread-in-group
    const int wr   = w >> 2;         // warp row-group (0..3): rows 32*wr..+31
    const int wc   = w & 3;          // warp unit-group (0..3): units 16*wc..+15
    const int row0 = blockIdx.x * ROWS;

    // ---------------- prologue ----------------
    for (int i = tid; i < (2 * A_BUFSZ) / 16; i += THREADS)
        *(uint4*)(smem_c + A_OFF + i * 16) = make_uint4(0, 0, 0, 0);

    // per-thread x tables (group wr owns rows 32wr..+31; 736 quads/group)
    const int ltid = wc * 32 + lane;              // 0..127 within group
    int nv = 736 - ltid * 6;
    nv = nv < 0 ? 0 : (nv > 6 ? 6 : nv);
    uint goffs[6], aoffs[6];
    #pragma unroll
    for (int j = 0; j < 6; ++j) {
        int s  = ltid * 6 + j;
        int rl = s / 23, q = s - rl * 23;
        int r  = wr * 32 + (rl & 31);
        goffs[j] = (uint)((((row0 + r) * T_LEN) * F_DIM + q * 4) * 4);  // bytes, t=0
        aoffs[j] = (uint)a_addr(r, 4 * q);
    }

    // W -> fp16 frag-permuted SMEM (paired-ng layout for LDS.128 B loads)
    for (int idx = tid; idx < KP * G_DIM; idx += THREADS) {
        int n = idx & 255, k = idx >> 8;
        float v;
        if (k < F_DIM)       v = Wk[k * G_DIM + n];
        else if (k < 96)     v = 0.0f;
        else                 v = Wr[(k - 96) * G_DIM + n];
        int kc = k >> 4, kr = k & 15;
        int gate = n >> 6, wcs = (n >> 4) & 3, ng = (n >> 3) & 1, gs = n & 7;
        int tts = (kr >> 1) & 3;
        int pos = ((kr >> 3) << 2) + ((kr & 1) << 1);
        int addr = W_OFF + kc * 8192 + (wcs * 4 + gate) * 512
                 + (gs * 4 + tts) * 16 + ng * 8 + pos;
        *(__half*)(smem_c + addr) = __float2half_rn(v);
    }
    if (tid < G_DIM) sb[tid] = b[tid];
    if (tid < H_DIM * 2) sWd[tid] = Wd[tid];

    // x(t=0): direct LDG -> convert -> A buf0
    {
        const char* xb = (const char*)x;
        #pragma unroll
        for (int j = 0; j < 6; ++j) {
            if (j < nv) {
                float4 v = *(const float4*)(xb + goffs[j]);
                *(uint*)(smem_c + A_OFF + aoffs[j])      = pack_h2(v.x, v.y);
                *(uint*)(smem_c + A_OFF + aoffs[j] + 16) = pack_h2(v.z, v.w);
            }
        }
    }
    __syncthreads();

    float c_st[16];
    #pragma unroll
    for (int i = 0; i < 16; ++i) c_st[i] = 0.0f;

    // ---------------- time loop ----------------
    #pragma unroll 1
    for (int t = 0; t < T_LEN; ++t) {
        const char* abr = smem_c + A_OFF + (t & 1) * A_BUFSZ;
        char*       abw = smem_c + A_OFF + ((t & 1) ^ 1) * A_BUFSZ;

        // acc[mt][gate*2+ng][4], init = bias
        float acc[2][8][4];
        #pragma unroll
        for (int j = 0; j < 8; ++j) {
            int gate = j >> 1, ng = j & 1;
            int col = gate * 64 + wc * 16 + ng * 8 + 2 * tt;
            float2 bv = *(const float2*)(sb + col);
            #pragma unroll
            for (int mt = 0; mt < 2; ++mt) {
                acc[mt][j][0] = bv.x; acc[mt][j][1] = bv.y;
                acc[mt][j][2] = bv.x; acc[mt][j][3] = bv.y;
            }
        }

        // MMA over 10 K-chunks (reads buffer t&1, rows 32wr..+31 only)
        #pragma unroll
        for (int kc = 0; kc < NKC; ++kc) {
            int a0off = (((2 * wr + 0) * NKC + kc) * 32 + lane) << 4;
            int a1off = (((2 * wr + 1) * NKC + kc) * 32 + lane) << 4;
            uint4 a0 = *(const uint4*)(abr + a0off);
            uint4 a1 = *(const uint4*)(abr + a1off);
            const char* wb = smem_c + W_OFF + kc * 8192 + wc * 2048 + (g * 4 + tt) * 16;
            #pragma unroll
            for (int gate = 0; gate < 4; ++gate) {
                uint4 bq = *(const uint4*)(wb + gate * 512);
                mma16816(acc[0][gate * 2 + 0], a0, bq.x, bq.y);
                mma16816(acc[0][gate * 2 + 1], a0, bq.z, bq.w);
                mma16816(acc[1][gate * 2 + 0], a1, bq.x, bq.y);
                mma16816(acc[1][gate * 2 + 1], a1, bq.z, bq.w);
            }
        }

        // issue x(t+1) LDGs now; latency hides under the epilogue
        float4 xq0, xq1, xq2, xq3, xq4, xq5;
        if (t + 1 < T_LEN) {
            const char* xb = (const char*)x + (size_t)(t + 1) * (F_DIM * 4);
            if (0 < nv) xq0 = *(const float4*)(xb + goffs[0]);
            if (1 < nv) xq1 = *(const float4*)(xb + goffs[1]);
            if (2 < nv) xq2 = *(const float4*)(xb + goffs[2]);
            if (3 < nv) xq3 = *(const float4*)(xb + goffs[3]);
            if (4 < nv) xq4 = *(const float4*)(xb + goffs[4]);
            if (5 < nv) xq5 = *(const float4*)(xb + goffs[5]);
        }

        // epilogue (f16x2 gates, fp32 c-state): gates -> c,h ; write h(t)
        #pragma unroll
        for (int mt = 0; mt < 2; ++mt) {
            int mtg = wr * 2 + mt;
            #pragma unroll
            for (int ng = 0; ng < 2; ++ng) {
                uint hout[2];
                #pragma unroll
                for (int p = 0; p < 2; ++p) {
                    int s0 = 2 * p, s1 = 2 * p + 1;
                    uint i2 = sig2u(acc[mt][0 + ng][s0], acc[mt][0 + ng][s1]);
                    uint f2 = sig2u(acc[mt][2 + ng][s0], acc[mt][2 + ng][s1]);
                    uint g2 = htanh2u(pack_h2(acc[mt][4 + ng][s0], acc[mt][4 + ng][s1]));
                    uint o2 = sig2u(acc[mt][6 + ng][s0], acc[mt][6 + ng][s1]);
                    float2 fi = h2f2(i2), ff = h2f2(f2), fg = h2f2(g2);
                    int ci = mt * 8 + ng * 4 + s0;
                    float cn0 = fmaf(ff.x, c_st[ci],     fi.x * fg.x);
                    float cn1 = fmaf(ff.y, c_st[ci + 1], fi.y * fg.y);
                    c_st[ci] = cn0; c_st[ci + 1] = cn1;
                    uint t2 = htanh2u(pack_h2(cn0, cn1));
                    __half2 hr = __hmul2(*(__half2*)&o2, *(__half2*)&t2);
                    hout[p] = *(uint*)&hr;
                }
                int k  = 96 + wc * 16 + ng * 8 + 2 * tt;
                int kc = k >> 4, kr = k & 15, tK = (kr >> 1) & 3;
                int base = (((mtg * NKC + kc) * 32 + g * 4 + tK) << 4) + ((kr >> 3) << 3);
                uint2 hq = make_uint2(hout[0], hout[1]);   // rows g, g+8
                *(uint2*)(abw + base) = hq;                // STS.64
            }
        }

        // convert x(t+1) registers -> write-buffer x-region (own rows only)
        if (t + 1 < T_LEN) {
            if (0 < nv) { *(uint*)(abw + aoffs[0])      = pack_h2(xq0.x, xq0.y);
                          *(uint*)(abw + aoffs[0] + 16) = pack_h2(xq0.z, xq0.w); }
            if (1 < nv) { *(uint*)(abw + aoffs[1])      = pack_h2(xq1.x, xq1.y);
                          *(uint*)(abw + aoffs[1] + 16) = pack_h2(xq1.z, xq1.w); }
            if (2 < nv) { *(uint*)(abw + aoffs[2])      = pack_h2(xq2.x, xq2.y);
                          *(uint*)(abw + aoffs[2] + 16) = pack_h2(xq2.z, xq2.w); }
            if (3 < nv) { *(uint*)(abw + aoffs[3])      = pack_h2(xq3.x, xq3.y);
                          *(uint*)(abw + aoffs[3] + 16) = pack_h2(xq3.z, xq3.w); }
            if (4 < nv) { *(uint*)(abw + aoffs[4])      = pack_h2(xq4.x, xq4.y);
                          *(uint*)(abw + aoffs[4] + 16) = pack_h2(xq4.z, xq4.w); }
            if (5 < nv) { *(uint*)(abw + aoffs[5])      = pack_h2(xq5.x, xq5.y);
                          *(uint*)(abw + aoffs[5] + 16) = pack_h2(xq5.z, xq5.w); }
        }

        // group-local barrier: only the 4 warps sharing rows 32wr..+31 must sync
        asm volatile("bar.sync %0, 128;" :: "r"(wr + 1) : "memory");
    }

    // ---------------- head ----------------
    __syncthreads();   // cross-group visibility of final h (buffer 0, T_LEN even)
    if (tid < ROWS * 2) {
        int r = tid >> 1, l = tid & 1;
        float s = bd[l];
        #pragma unroll
        for (int up = 0; up < 32; ++up) {
            int u = 2 * up;
            uint hb = *(uint*)(smem_c + A_OFF + a_addr(r, 96 + u));
            float2 hf = __half22float2(*(__half2*)&hb);
            s += hf.x * sWd[u * 2 + l] + hf.y * sWd[(u + 1) * 2 + l];
        }
        out[(size_t)(row0 + r) * 2 + l] = sig_acc(s);
    }
}

extern "C" void kernel_launch(void* const* d_in, const int* in_sizes, int n_in,
                              void* d_out, int out_size)
{
    const float* x  = (const float*)d_in[0];
    const float* Wk = (const float*)d_in[1];
    const float* Wr = (const float*)d_in[2];
    const float* b  = (const float*)d_in[3];
    const float* Wd = (const float*)d_in[4];
    const float* bd = (const float*)d_in[5];
    float* out = (float*)d_out;

    cudaFuncSetAttribute(lstm_hmma_kernel,
                         cudaFuncAttributeMaxDynamicSharedMemorySize, SMEM_BYTES);
    lstm_hmma_kernel<<<B_TOT / ROWS, THREADS, SMEM_BYTES>>>(x, Wk, Wr, b, Wd, bd, out);
}

// round 13
// speedup vs baseline: 1.1658x; 1.1658x over previous
#include <cuda_runtime.h>
#include <cuda_fp16.h>
#include <cstdint>

#define B_TOT   32768
#define T_LEN   40
#define F_DIM   92
#define H_DIM   64
#define G_DIM   256
#define ROWS    128
#define THREADS 512
#define KP      160      // k: 0..91 x, 92..95 pad, 96..159 h
#define NKC     10

// ---------------- SMEM byte offsets ----------------
#define W_OFF    0                 // fp16 W: [kc][blk=wc*4+gate][lane]{16B} : 10*16*512 = 81920
#define A_OFF    81920             // fp16 A frags x2 buffers: 2*40960
#define A_BUFSZ  40960
#define XS_OFF   163840            // fp32 x stage, group-linear slots: 4*736*16 = 47104
#define SB_OFF   210944            // bias fp32 [256] = 1024
#define SWD_OFF  211968            // Wd fp32 [64][2] = 512
#define SMEM_BYTES 212480

typedef unsigned int uint;

__device__ __forceinline__ uint32_t smem_u32(const void* p) {
    uint32_t a;
    asm("{ .reg .u64 t; cvta.to.shared.u64 t, %1; cvt.u32.u64 %0, t; }" : "=r"(a) : "l"(p));
    return a;
}
__device__ __forceinline__ void cp_async16(uint32_t dst, const void* src) {
    asm volatile("cp.async.cg.shared.global [%0], [%1], 16;" :: "r"(dst), "l"(src) : "memory");
}
#define CP_COMMIT() asm volatile("cp.async.commit_group;" ::: "memory")
#define CP_WAIT0()  asm volatile("cp.async.wait_group 0;" ::: "memory")

__device__ __forceinline__ void mma16816(float* d, const uint4& a, uint b0, uint b1) {
    asm volatile(
        "mma.sync.aligned.m16n8k16.row.col.f32.f16.f16.f32 "
        "{%0,%1,%2,%3}, {%4,%5,%6,%7}, {%8,%9}, {%0,%1,%2,%3};"
        : "+f"(d[0]), "+f"(d[1]), "+f"(d[2]), "+f"(d[3])
        : "r"(a.x), "r"(a.y), "r"(a.z), "r"(a.w), "r"(b0), "r"(b1));
}

// ---- f16x2 activation helpers ----
__device__ __forceinline__ uint htanh2u(uint x) {
    uint r; asm("tanh.approx.f16x2 %0, %1;" : "=r"(r) : "r"(x)); return r;
}
__device__ __forceinline__ uint pack_h2(float a, float b) {
    __half2 t = __floats2half2_rn(a, b);
    return *(uint*)&t;
}
// sigmoid(z0),sigmoid(z1) as half2: 0.5*tanh(0.5 z)+0.5
__device__ __forceinline__ uint sig2u(float z0, float z1) {
    uint th = htanh2u(pack_h2(0.5f * z0, 0.5f * z1));
    __half2 t = *(__half2*)&th;
    const __half2 h05 = __floats2half2_rn(0.5f, 0.5f);
    __half2 r = __hfma2(t, h05, h05);
    return *(uint*)&r;
}
__device__ __forceinline__ float2 h2f2(uint h) { return __half22float2(*(__half2*)&h); }

__device__ __forceinline__ float sig_acc(float x) { return 1.0f / (1.0f + __expf(-x)); }

// A-plane byte offset for element (row, k) within one buffer; k even pairs contiguous 4B
__device__ __forceinline__ int a_addr(int row, int k) {
    int mtg = row >> 4, r16 = row & 15, g = r16 & 7;
    int kc = k >> 4, kr = k & 15, tK = (kr >> 1) & 3;
    return (((mtg * NKC + kc) * 32 + g * 4 + tK) << 4) + ((kr >> 3) << 3) + ((r16 >> 3) << 2);
}

__global__ void __launch_bounds__(THREADS, 1)
lstm_hmma_kernel(const float* __restrict__ x,
                 const float* __restrict__ Wk,
                 const float* __restrict__ Wr,
                 const float* __restrict__ b,
                 const float* __restrict__ Wd,
                 const float* __restrict__ bd,
                 float* __restrict__ out)
{
    extern __shared__ char smem_c[];
    float* sb  = (float*)(smem_c + SB_OFF);
    float* sWd = (float*)(smem_c + SWD_OFF);
    const uint32_t sbase = smem_u32(smem_c);

    const int tid  = threadIdx.x;
    const int w    = tid >> 5;
    const int lane = tid & 31;
    const int g    = lane >> 2;      // mma group id
    const int tt   = lane & 3;       // thread-in-group
    const int wr   = w >> 2;         // warp row-group (0..3): rows 32*wr..+31
    const int wc   = w & 3;          // warp unit-group (0..3): units 16*wc..+15
    const int row0 = blockIdx.x * ROWS;
    const int bar_x = 1 + wr;        // named barrier ids
    const int bar_h = 5 + wr;

    // ---------------- prologue ----------------
    for (int i = tid; i < (2 * A_BUFSZ) / 16; i += THREADS)
        *(uint4*)(smem_c + A_OFF + i * 16) = make_uint4(0, 0, 0, 0);

    // per-thread x-staging tables (group wr owns rows 32wr..+31; 736 quads/group)
    const int ltid = wc * 32 + lane;              // 0..127 within group
    int nv = 736 - ltid * 6;
    nv = nv < 0 ? 0 : (nv > 6 ? 6 : nv);
    uint goffs[6], aoffs[6];
    #pragma unroll
    for (int j = 0; j < 6; ++j) {
        int s  = ltid * 6 + j;
        int rl = s / 23, q = s - rl * 23;
        int r  = wr * 32 + (rl & 31);
        goffs[j] = (uint)((((row0 + r) * T_LEN) * F_DIM + q * 4) * 4);  // bytes, t=0
        aoffs[j] = (uint)a_addr(r, 4 * q);
    }
    const uint32_t xsb = sbase + XS_OFF + (uint)(wr * 736 + ltid * 6) * 16;
    const char*    xsr = smem_c + XS_OFF + (wr * 736 + ltid * 6) * 16;

    // cp.async x(t=0)
    #pragma unroll
    for (int j = 0; j < 6; ++j)
        if (j < nv) cp_async16(xsb + j * 16, (const char*)x + goffs[j]);
    CP_COMMIT();

    // W -> fp16 frag-permuted SMEM (paired-ng layout for LDS.128 B loads)
    for (int idx = tid; idx < KP * G_DIM; idx += THREADS) {
        int n = idx & 255, k = idx >> 8;
        float v;
        if (k < F_DIM)       v = Wk[k * G_DIM + n];
        else if (k < 96)     v = 0.0f;
        else                 v = Wr[(k - 96) * G_DIM + n];
        int kc = k >> 4, kr = k & 15;
        int gate = n >> 6, wcs = (n >> 4) & 3, ng = (n >> 3) & 1, gs = n & 7;
        int tts = (kr >> 1) & 3;
        int pos = ((kr >> 3) << 2) + ((kr & 1) << 1);
        int addr = W_OFF + kc * 8192 + (wcs * 4 + gate) * 512
                 + (gs * 4 + tts) * 16 + ng * 8 + pos;
        *(__half*)(smem_c + addr) = __float2half_rn(v);
    }
    if (tid < G_DIM) sb[tid] = b[tid];
    if (tid < H_DIM * 2) sWd[tid] = Wd[tid];

    // convert own quads: XS -> A buf0 x-region
    CP_WAIT0();
    #pragma unroll
    for (int j = 0; j < 6; ++j) {
        if (j < nv) {
            float4 v = *(const float4*)(xsr + j * 16);
            *(uint*)(smem_c + A_OFF + aoffs[j])      = pack_h2(v.x, v.y);
            *(uint*)(smem_c + A_OFF + aoffs[j] + 16) = pack_h2(v.z, v.w);
        }
    }
    __syncthreads();

    float c_st[16];
    #pragma unroll
    for (int i = 0; i < 16; ++i) c_st[i] = 0.0f;

    // ---------------- time loop (split-barrier pipeline) ----------------
    #pragma unroll 1
    for (int t = 0; t < T_LEN; ++t) {
        const char* abr = smem_c + A_OFF + (t & 1) * A_BUFSZ;
        char*       abw = smem_c + A_OFF + ((t & 1) ^ 1) * A_BUFSZ;

        // prefetch x(t+1) -> own XS slots (in flight across the whole MMA phase)
        if (t + 1 < T_LEN) {
            const char* xb = (const char*)x + (size_t)(t + 1) * (F_DIM * 4);
            #pragma unroll
            for (int j = 0; j < 6; ++j)
                if (j < nv) cp_async16(xsb + j * 16, xb + goffs[j]);
            CP_COMMIT();
        }

        // acc[mt][gate*2+ng][4], init = bias
        float acc[2][8][4];
        #pragma unroll
        for (int j = 0; j < 8; ++j) {
            int gate = j >> 1, ng = j & 1;
            int col = gate * 64 + wc * 16 + ng * 8 + 2 * tt;
            float2 bv = *(const float2*)(sb + col);
            #pragma unroll
            for (int mt = 0; mt < 2; ++mt) {
                acc[mt][j][0] = bv.x; acc[mt][j][1] = bv.y;
                acc[mt][j][2] = bv.x; acc[mt][j][3] = bv.y;
            }
        }

        // ---- wait x(t) ready, then x-part MMA (kc 0..5) ----
        if (t > 0) asm volatile("bar.sync %0, 256;" :: "r"(bar_x) : "memory");
        #pragma unroll
        for (int kc = 0; kc < 6; ++kc) {
            int a0off = (((2 * wr + 0) * NKC + kc) * 32 + lane) << 4;
            int a1off = (((2 * wr + 1) * NKC + kc) * 32 + lane) << 4;
            uint4 a0 = *(const uint4*)(abr + a0off);
            uint4 a1 = *(const uint4*)(abr + a1off);
            const char* wb = smem_c + W_OFF + kc * 8192 + wc * 2048 + (g * 4 + tt) * 16;
            #pragma unroll
            for (int gate = 0; gate < 4; ++gate) {
                uint4 bq = *(const uint4*)(wb + gate * 512);
                mma16816(acc[0][gate * 2 + 0], a0, bq.x, bq.y);
                mma16816(acc[0][gate * 2 + 1], a0, bq.z, bq.w);
                mma16816(acc[1][gate * 2 + 0], a1, bq.x, bq.y);
                mma16816(acc[1][gate * 2 + 1], a1, bq.z, bq.w);
            }
        }

        // ---- wait h(t-1) ready (deferred), then h-part MMA (kc 6..9) ----
        if (t > 0) asm volatile("bar.sync %0, 256;" :: "r"(bar_h) : "memory");
        #pragma unroll
        for (int kc = 6; kc < NKC; ++kc) {
            int a0off = (((2 * wr + 0) * NKC + kc) * 32 + lane) << 4;
            int a1off = (((2 * wr + 1) * NKC + kc) * 32 + lane) << 4;
            uint4 a0 = *(const uint4*)(abr + a0off);
            uint4 a1 = *(const uint4*)(abr + a1off);
            const char* wb = smem_c + W_OFF + kc * 8192 + wc * 2048 + (g * 4 + tt) * 16;
            #pragma unroll
            for (int gate = 0; gate < 4; ++gate) {
                uint4 bq = *(const uint4*)(wb + gate * 512);
                mma16816(acc[0][gate * 2 + 0], a0, bq.x, bq.y);
                mma16816(acc[0][gate * 2 + 1], a0, bq.z, bq.w);
                mma16816(acc[1][gate * 2 + 0], a1, bq.x, bq.y);
                mma16816(acc[1][gate * 2 + 1], a1, bq.z, bq.w);
            }
        }

        // ---- convert x(t+1) -> write-buffer x-region; publish early ----
        if (t + 1 < T_LEN) {
            CP_WAIT0();
            #pragma unroll
            for (int j = 0; j < 6; ++j) {
                if (j < nv) {
                    float4 v = *(const float4*)(xsr + j * 16);
                    *(uint*)(abw + aoffs[j])      = pack_h2(v.x, v.y);
                    *(uint*)(abw + aoffs[j] + 16) = pack_h2(v.z, v.w);
                }
            }
            asm volatile("membar.cta;" ::: "memory");
            asm volatile("bar.arrive %0, 256;" :: "r"(bar_x) : "memory");
        }

        // ---- epilogue (f16x2 gates, fp32 c-state): gates -> c,h ; write h(t) ----
        #pragma unroll
        for (int mt = 0; mt < 2; ++mt) {
            int mtg = wr * 2 + mt;
            #pragma unroll
            for (int ng = 0; ng < 2; ++ng) {
                uint hout[2];
                #pragma unroll
                for (int p = 0; p < 2; ++p) {
                    int s0 = 2 * p, s1 = 2 * p + 1;
                    uint i2 = sig2u(acc[mt][0 + ng][s0], acc[mt][0 + ng][s1]);
                    uint f2 = sig2u(acc[mt][2 + ng][s0], acc[mt][2 + ng][s1]);
                    uint g2 = htanh2u(pack_h2(acc[mt][4 + ng][s0], acc[mt][4 + ng][s1]));
                    uint o2 = sig2u(acc[mt][6 + ng][s0], acc[mt][6 + ng][s1]);
                    float2 fi = h2f2(i2), ff = h2f2(f2), fg = h2f2(g2);
                    int ci = mt * 8 + ng * 4 + s0;
                    float cn0 = fmaf(ff.x, c_st[ci],     fi.x * fg.x);
                    float cn1 = fmaf(ff.y, c_st[ci + 1], fi.y * fg.y);
                    c_st[ci] = cn0; c_st[ci + 1] = cn1;
                    uint t2 = htanh2u(pack_h2(cn0, cn1));
                    __half2 hr = __hmul2(*(__half2*)&o2, *(__half2*)&t2);
                    hout[p] = *(uint*)&hr;
                }
                int k  = 96 + wc * 16 + ng * 8 + 2 * tt;
                int kc = k >> 4, kr = k & 15, tK = (kr >> 1) & 3;
                int base = (((mtg * NKC + kc) * 32 + g * 4 + tK) << 4) + ((kr >> 3) << 3);
                uint2 hq = make_uint2(hout[0], hout[1]);   // rows g, g+8
                *(uint2*)(abw + base) = hq;                // STS.64
            }
        }
        if (t + 1 < T_LEN) {
            asm volatile("membar.cta;" ::: "memory");
            asm volatile("bar.arrive %0, 256;" :: "r"(bar_h) : "memory");
        }
    }

    // ---------------- head ----------------
    __syncthreads();   // cross-group + final-write visibility (h(39) in buffer 0)
    if (tid < ROWS * 2) {
        int r = tid >> 1, l = tid & 1;
        float s = bd[l];
        #pragma unroll
        for (int up = 0; up < 32; ++up) {
            int u = 2 * up;
            uint hb = *(uint*)(smem_c + A_OFF + a_addr(r, 96 + u));
            float2 hf = __half22float2(*(__half2*)&hb);
            s += hf.x * sWd[u * 2 + l] + hf.y * sWd[(u + 1) * 2 + l];
        }
        out[(size_t)(row0 + r) * 2 + l] = sig_acc(s);
    }
}

extern "C" void kernel_launch(void* const* d_in, const int* in_sizes, int n_in,
                              void* d_out, int out_size)
{
    const float* x  = (const float*)d_in[0];
    const float* Wk = (const float*)d_in[1];
    const float* Wr = (const float*)d_in[2];
    const float* b  = (const float*)d_in[3];
    const float* Wd = (const float*)d_in[4];
    const float* bd = (const float*)d_in[5];
    float* out = (float*)d_out;

    cudaFuncSetAttribute(lstm_hmma_kernel,
                         cudaFuncAttributeMaxDynamicSharedMemorySize, SMEM_BYTES);
    lstm_hmma_kernel<<<B_TOT / ROWS, THREADS, SMEM_BYTES>>>(x, Wk, Wr, b, Wd, bd, out);
}